// round 2
// baseline (speedup 1.0000x reference)
#include <cuda_runtime.h>

#define SEQ   4096
#define BATCH 4096
#define NIN   2
#define HID   8
#define CTAS  128
#define BPC   (BATCH / CTAS)   // 32 batches per CTA
#define TPB   (BPC * HID)      // 256 threads

__device__ __forceinline__ float ex2f_(float x) {
    float y; asm("ex2.approx.f32 %0, %1;" : "=f"(y) : "f"(x)); return y;
}
__device__ __forceinline__ float rcpf_(float x) {
    float y; asm("rcp.approx.f32 %0, %1;" : "=f"(y) : "f"(x)); return y;
}

// Packed fp32x2 FMA (Blackwell): d = a*b + c on both halves, one instruction.
__device__ __forceinline__ float2 ffma2(float2 a, float2 b, float2 c) {
    float2 d;
    asm("{\n\t"
        ".reg .b64 ra, rb, rc, rd;\n\t"
        "mov.b64 ra, {%2, %3};\n\t"
        "mov.b64 rb, {%4, %5};\n\t"
        "mov.b64 rc, {%6, %7};\n\t"
        "fma.rn.f32x2 rd, ra, rb, rc;\n\t"
        "mov.b64 {%0, %1}, rd;\n\t"
        "}"
        : "=f"(d.x), "=f"(d.y)
        : "f"(a.x), "f"(a.y), "f"(b.x), "f"(b.y), "f"(c.x), "f"(c.y));
    return d;
}

__global__ void __launch_bounds__(TPB) lstm_kernel(
    const float* __restrict__ x,
    const float* __restrict__ h0,
    const float* __restrict__ c0,
    const float* __restrict__ W_ih,
    const float* __restrict__ W_hh,
    const float* __restrict__ b_ih,
    const float* __restrict__ b_hh,
    float* __restrict__ out)
{
    const int tid = threadIdx.x;
    const int g   = tid >> 3;   // batch group within CTA, 0..31
    const int j   = tid & 7;    // h index, 0..7
    const int b   = blockIdx.x * BPC + g;

    const float LOG2E = 1.4426950408889634f;
    // Gate rows owned by this lane (PyTorch order i,f,g,o)
    const int ri = j, rf = 8 + j, rg = 16 + j, ro = 24 + j;
    // Fold activation argument scaling into the weights:
    //   sigmoid(u) = rcp(1 + exp2(-u*log2e))      -> scale rows i,f,o by -log2e
    //   tanh(u)    = 2*rcp(1 + exp2(-2u*log2e))-1 -> scale row g by -2*log2e
    const float si = -LOG2E, sf = -LOG2E, sg = -2.0f * LOG2E, so = -LOG2E;

    // Pair-packed weights: (i,f) pair and (g,o) pair
    float2 wif_h[HID], wgo_h[HID];
    #pragma unroll
    for (int k = 0; k < HID; k++) {
        wif_h[k] = make_float2(si * W_hh[ri * HID + k], sf * W_hh[rf * HID + k]);
        wgo_h[k] = make_float2(sg * W_hh[rg * HID + k], so * W_hh[ro * HID + k]);
    }
    const float2 wif_x0 = make_float2(si * W_ih[ri * NIN + 0], sf * W_ih[rf * NIN + 0]);
    const float2 wif_x1 = make_float2(si * W_ih[ri * NIN + 1], sf * W_ih[rf * NIN + 1]);
    const float2 wgo_x0 = make_float2(sg * W_ih[rg * NIN + 0], so * W_ih[ro * NIN + 0]);
    const float2 wgo_x1 = make_float2(sg * W_ih[rg * NIN + 1], so * W_ih[ro * NIN + 1]);
    const float2 bif = make_float2(si * (b_ih[ri] + b_hh[ri]), sf * (b_ih[rf] + b_hh[rf]));
    const float2 bgo = make_float2(sg * (b_ih[rg] + b_hh[rg]), so * (b_ih[ro] + b_hh[ro]));

    // h exchange: duplicated pairs (h,h) so LDS.128 returns ready f32x2 multipliers.
    // Double-buffered; all consumers of a group's region are in the same warp.
    __shared__ __align__(16) float2 sh[2][BPC][HID];

    float c = c0[b * HID + j];
    float h = h0[b * HID + j];
    sh[0][g][j] = make_float2(h, h);
    __syncwarp();

    const size_t xstride = (size_t)BATCH * NIN;
    const float* xbase = x + (size_t)b * NIN;

    auto ldx = [&](int s) -> float2 {
        return *(const float2*)(xbase + (size_t)s * xstride);
    };

    auto dostep = [&](float2 xv, int rd) {
        // Gather 8 duplicated h pairs (64B broadcast within the 8-lane group)
        const float4* hp = (const float4*)&sh[rd][g][0];
        float4 a0 = hp[0], a1 = hp[1], a2 = hp[2], a3 = hp[3];

        float2 x0d = make_float2(xv.x, xv.x);
        float2 x1d = make_float2(xv.y, xv.y);

        float2 aif = ffma2(wif_x0, x0d, bif);
        float2 ago = ffma2(wgo_x0, x0d, bgo);
        aif = ffma2(wif_x1, x1d, aif);
        ago = ffma2(wgo_x1, x1d, ago);

        float2 d0 = make_float2(a0.x, a0.y), d1 = make_float2(a0.z, a0.w);
        float2 d2 = make_float2(a1.x, a1.y), d3 = make_float2(a1.z, a1.w);
        float2 d4 = make_float2(a2.x, a2.y), d5 = make_float2(a2.z, a2.w);
        float2 d6 = make_float2(a3.x, a3.y), d7 = make_float2(a3.z, a3.w);

        aif = ffma2(wif_h[0], d0, aif);  ago = ffma2(wgo_h[0], d0, ago);
        aif = ffma2(wif_h[1], d1, aif);  ago = ffma2(wgo_h[1], d1, ago);
        aif = ffma2(wif_h[2], d2, aif);  ago = ffma2(wgo_h[2], d2, ago);
        aif = ffma2(wif_h[3], d3, aif);  ago = ffma2(wgo_h[3], d3, ago);
        aif = ffma2(wif_h[4], d4, aif);  ago = ffma2(wgo_h[4], d4, ago);
        aif = ffma2(wif_h[5], d5, aif);  ago = ffma2(wgo_h[5], d5, ago);
        aif = ffma2(wif_h[6], d6, aif);  ago = ffma2(wgo_h[6], d6, ago);
        aif = ffma2(wif_h[7], d7, aif);  ago = ffma2(wgo_h[7], d7, ago);

        // Activations (scales pre-folded into weights)
        float s_i = rcpf_(1.0f + ex2f_(aif.x));
        float s_f = rcpf_(1.0f + ex2f_(aif.y));
        float t_g = fmaf(2.0f, rcpf_(1.0f + ex2f_(ago.x)), -1.0f);
        float s_o = rcpf_(1.0f + ex2f_(ago.y));

        c = s_f * c + s_i * t_g;
        float ec = ex2f_(c * (-2.0f * LOG2E));
        float t_c = fmaf(2.0f, rcpf_(1.0f + ec), -1.0f);
        h = s_o * t_c;

        sh[rd ^ 1][g][j] = make_float2(h, h);
        __syncwarp();
    };

    // Software pipeline x loads 4 steps ahead (DRAM latency ~577 cyc, step ~160 cyc)
    float2 xv0 = ldx(0), xv1 = ldx(1), xv2 = ldx(2), xv3 = ldx(3);

    #pragma unroll 1
    for (int s = 0; s < SEQ; s += 4) {
        dostep(xv0, 0);
        xv0 = ldx(s + 4 < SEQ ? s + 4 : SEQ - 1);
        dostep(xv1, 1);
        xv1 = ldx(s + 5 < SEQ ? s + 5 : SEQ - 1);
        dostep(xv2, 0);
        xv2 = ldx(s + 6 < SEQ ? s + 6 : SEQ - 1);
        dostep(xv3, 1);
        xv3 = ldx(s + 7 < SEQ ? s + 7 : SEQ - 1);
    }

    out[b * HID + j] = h;
}

extern "C" void kernel_launch(void* const* d_in, const int* in_sizes, int n_in,
                              void* d_out, int out_size) {
    const float* x    = (const float*)d_in[0];
    const float* h0   = (const float*)d_in[1];
    const float* c0   = (const float*)d_in[2];
    const float* W_ih = (const float*)d_in[3];
    const float* W_hh = (const float*)d_in[4];
    const float* b_ih = (const float*)d_in[5];
    const float* b_hh = (const float*)d_in[6];
    lstm_kernel<<<CTAS, TPB>>>(x, h0, c0, W_ih, W_hh, b_ih, b_hh, (float*)d_out);
}